// round 17
// baseline (speedup 1.0000x reference)
#include <cuda_runtime.h>
#include <cuda_fp16.h>

// ---------------------------------------------------------------------------
// InterpolatingBSpline2d, round 11: R7 chassis + de-serialized prologue.
//
// R7 (35.4us) = fused kernel, fp16 dual shifted-copy table, per-thread
// 8x LDS.128 gather, 1024x296. Accounting showed ~8-11us spent in the
// prologue vs a ~1.5us work model: in-place Thomas loops interleave smem
// loads/stores on the same object (+volatile), so ptxas serialized every
// iteration on a ~30cyc LDS round-trip.
//
// Fixes (gather untouched):
//  * chunked recurrences: load-8 -> compute-8 -> store-8. True RAW kept by
//    in-chunk order; across chunks the >=2-slot slack makes loads/stores
//    provably disjoint, so loads batch into one latency window.
//  * region-swapped half outputs, no volatile: stage-2 writes c01 halfs into
//    copy1's region and c23 halfs into copy0's region (disjoint from its own
//    load stream). Cross-lane clobbers keep the slack-2 lockstep discipline
//    (same as R7, empirically exact across rounds).
//  * merge pass (read -> sync -> write, values in regs) assembles the final
//    dual-copy layout: copy0 slot y = {c01(y), c23(y)}, copy1 slot y =
//    {c01(y+1), c23(y+1)}. Replaces the old shift loop.
// ---------------------------------------------------------------------------

#define M_GRID   64
#define NP2      66
#define NINNER   62
#define NCH      4
#define ROW_F    132                      // u32/floats per (jx,copy) row
#define ROW_H    264                      // halfs per row
#define NSLOT    (NP2 * NP2)              // 4356
#define COPY_HALFS (NSLOT * NCH)          // 17424 halfs per copy
#define COPY_F   (COPY_HALFS / 2)         // 8712 floats per copy region
#define SMEM_BYTES (2 * COPY_HALFS * 2)   // 69,696

// ---- compile-time Thomas factors ------------------------------------------
struct Fac { float cp[NINNER]; float invden[NINNER]; };

constexpr Fac make_fac() {
    Fac f{};
    const float B = 2.0f / 3.0f, A = 1.0f / 6.0f;
    float c = A / B;
    f.cp[0] = c;
    f.invden[0] = 1.0f / B;
    for (int m = 1; m < NINNER; ++m) {
        float den = B - A * c;
        float inv = 1.0f / den;
        c = A * inv;
        f.cp[m] = c;
        f.invden[m] = inv;
    }
    return f;
}
__constant__ Fac FAC = make_fac();

__device__ __forceinline__ unsigned short f2h(float v)
{
    return __half_as_ushort(__float2half_rn(v));
}

__device__ __forceinline__ float2 h2f(unsigned v)
{
    __half2 h = *reinterpret_cast<const __half2*>(&v);
    return __half22float2(h);
}

__global__ void __launch_bounds__(1024, 2) bspline_fused(
    const float* __restrict__ data,
    const float2* __restrict__ u,
    float4* __restrict__ out, int n)
{
    extern __shared__ __align__(16) float sf[];     // 69,696 B
    __half* sh = reinterpret_cast<__half*>(sf);
    const int t = threadIdx.x;
    const float S = 1.0f / 6.0f;

    // ======== stage 1: solve along x (256 threads, one (c,my) chain) ========
    if (t < 256) {
        const int c  = t >> 6;
        const int my = t & 63;
        const float* src = data + c * (M_GRID * M_GRID) + my;   // stride 64
        float* B = sf + ((c & 2) ? COPY_F : 0) + 2 * my + (c & 1);

        float d0 = src[0];
        float a  = (src[64] - d0 * S) * FAC.invden[0];
        B[0] = a;                                   // dp[0]
#pragma unroll
        for (int m = 1; m <= 60; ++m) {             // global loads batch freely
            a = (src[(m + 1) * 64] - a * S) * FAC.invden[m];
            B[m * ROW_F] = a;                       // dp[m]
        }
        float d63 = src[63 * 64];
        a = (src[62 * 64] - d63 * S - a * S) * FAC.invden[61];  // dp[61]

        float z = a;                                // x63
        B[65 * ROW_F] = 2.0f * d63 - z;
        B[64 * ROW_F] = d63;
        B[63 * ROW_F] = z;
        // chunked backward sweep: m = 60..5 (7x8), then 4..0
#pragma unroll
        for (int cb = 0; cb < 7; ++cb) {
            float v[8];
#pragma unroll
            for (int j = 0; j < 8; ++j)
                v[j] = B[(60 - 8 * cb - j) * ROW_F];        // dp[m]
#pragma unroll
            for (int j = 0; j < 8; ++j) {
                int m = 60 - 8 * cb - j;
                z = v[j] - FAC.cp[m] * z;
                B[(m + 2) * ROW_F] = z;                     // slack-2, own-thread
            }
        }
        {
            float v[5];
#pragma unroll
            for (int j = 0; j < 5; ++j) v[j] = B[(4 - j) * ROW_F];
#pragma unroll
            for (int j = 0; j < 5; ++j) {
                int m = 4 - j;
                z = v[j] - FAC.cp[m] * z;
                B[(m + 2) * ROW_F] = z;
            }
        }
        B[ROW_F] = d0;                              // x1
        B[0]     = 2.0f * d0 - z;                   // x0 (z holds x2)
    }
    __syncthreads();

    // ======== stage 2: solve along y (264 threads, t = 4*jx + c) ========
    // Scratch region: c01 -> copy0, c23 -> copy1 (as stage 1 left it).
    // Half OUTPUT region is SWAPPED: c01 halfs -> copy1, c23 halfs -> copy0,
    // so this thread's load/store streams are disjoint (no volatile needed).
    if (t < NCH * NP2) {
        const int jx = t >> 2, c = t & 3;
        float* R = sf + ((c & 2) ? COPY_F : 0) + jx * ROW_F + (c & 1);
        unsigned short* T = reinterpret_cast<unsigned short*>(sh)
                          + ((c & 2) ? 0 : COPY_HALFS) + jx * ROW_H + c;

        float d0 = R[0];
        float carry = (R[2] - d0 * S) * FAC.invden[0];
        R[0] = carry;                               // dp[0]
        // chunked forward: m = 1..56 (7x8), then 57..60
#pragma unroll
        for (int cb = 0; cb < 7; ++cb) {
            float v[8];
#pragma unroll
            for (int j = 0; j < 8; ++j)
                v[j] = R[(2 + 8 * cb + j) * 2];             // sample m+1
#pragma unroll
            for (int j = 0; j < 8; ++j) {
                int m = 1 + 8 * cb + j;
                carry = (v[j] - carry * S) * FAC.invden[m];
                R[m * 2] = carry;                           // dp[m]
            }
        }
        {
            float v[4];
#pragma unroll
            for (int j = 0; j < 4; ++j) v[j] = R[(58 + j) * 2];
#pragma unroll
            for (int j = 0; j < 4; ++j) {
                int m = 57 + j;
                carry = (v[j] - carry * S) * FAC.invden[m];
                R[m * 2] = carry;
            }
        }
        float s62 = R[62 * 2], d63 = R[63 * 2];
        carry = (s62 - d63 * S - carry * S) * FAC.invden[61];   // dp[61]

        float z = carry;                            // x63
        T[65 * 4] = f2h(2.0f * d63 - z);            // y=65
        T[64 * 4] = f2h(d63);                       // y=64
        T[63 * 4] = f2h(z);                         // y=63
        // chunked backward: m = 60..5 (7x8), then 4..0
#pragma unroll
        for (int cb = 0; cb < 7; ++cb) {
            float v[8];
#pragma unroll
            for (int j = 0; j < 8; ++j)
                v[j] = R[(60 - 8 * cb - j) * 2];            // dp[m]
#pragma unroll
            for (int j = 0; j < 8; ++j) {
                int m = 60 - 8 * cb - j;
                z = v[j] - FAC.cp[m] * z;
                T[(m + 2) * 4] = f2h(z);                    // other region
            }
        }
        {
            float v[5];
#pragma unroll
            for (int j = 0; j < 5; ++j) v[j] = R[(4 - j) * 2];
#pragma unroll
            for (int j = 0; j < 5; ++j) {
                int m = 4 - j;
                z = v[j] - FAC.cp[m] * z;
                T[(m + 2) * 4] = f2h(z);
            }
        }
        T[4] = f2h(d0);                             // y=1
        T[0] = f2h(2.0f * d0 - z);                  // y=0 (z holds x2)
    }
    __syncthreads();

    // ======== merge: assemble final dual-copy layout ========
    // After stage 2: A(jx,y) = c01 pair at U[COPY_F + jx*132 + 2y],
    //                B(jx,y) = c23 pair at U[jx*132 + 2y + 1] (already final).
    // Final: U[jx*132+2y] = A(y); U[COPY_F+jx*132+2y] = A(y+1);
    //        U[COPY_F+jx*132+2y+1] = B(y+1).
    {
        unsigned* U = reinterpret_cast<unsigned*>(sf);
        unsigned a0[5], a1[5], b1[5];
#pragma unroll
        for (int q = 0; q < 5; ++q) {
            int it = t + q * 1024;
            if (it < NSLOT) {
                int jx = it / NP2, y = it - jx * NP2;
                int r1 = COPY_F + jx * ROW_F + 2 * y;
                a0[q] = U[r1];
                if (y < 65) {
                    a1[q] = U[r1 + 2];
                    b1[q] = U[jx * ROW_F + 2 * y + 3];
                }
            }
        }
        __syncthreads();
#pragma unroll
        for (int q = 0; q < 5; ++q) {
            int it = t + q * 1024;
            if (it < NSLOT) {
                int jx = it / NP2, y = it - jx * NP2;
                int r0 = jx * ROW_F + 2 * y;
                U[r0] = a0[q];
                if (y < 65) {
                    U[COPY_F + r0]     = a1[q];
                    U[COPY_F + r0 + 1] = b1[q];
                }
            }
        }
    }
    __syncthreads();

    // ======== gather (R7 loop, unchanged) ========
    int stride = gridDim.x * blockDim.x;
    for (int i = blockIdx.x * blockDim.x + t; i < n; i += stride) {
        float2 p = u[i];
        float uxn = p.x * 63.0f;
        float fx  = floorf(uxn);
        int   ix  = (int)fx;
        float tx  = uxn - fx;
        if (uxn < 0.0f)   { ix = 0;  tx = uxn; }
        if (uxn >= 62.0f) { ix = 62; tx = uxn - 62.0f; }

        float uyn = p.y * 63.0f;
        float fy  = floorf(uyn);
        int   iy  = (int)fy;
        float ty  = uyn - fy;
        if (uyn < 0.0f)   { iy = 0;  ty = uyn; }
        if (uyn >= 62.0f) { iy = 62; ty = uyn - 62.0f; }

        float wx0 = ((-S * tx + 0.5f) * tx - 0.5f) * tx + S;
        float wx1 = ((0.5f * tx - 1.0f) * tx) * tx + (2.0f / 3.0f);
        float wx2 = ((-0.5f * tx + 0.5f) * tx + 0.5f) * tx + S;
        float wx3 = (S * tx) * tx * tx;

        float wy0 = ((-S * ty + 0.5f) * ty - 0.5f) * ty + S;
        float wy1 = ((0.5f * ty - 1.0f) * ty) * ty + (2.0f / 3.0f);
        float wy2 = ((-0.5f * ty + 0.5f) * ty + 0.5f) * ty + S;
        float wy3 = (S * ty) * ty * ty;

        int iy2 = iy & ~1;
        const uint4* bp = reinterpret_cast<const uint4*>(
            sh + (iy & 1) * COPY_HALFS + (ix * NP2 + iy2) * NCH);

        float acc0 = 0.0f, acc1 = 0.0f, acc2 = 0.0f, acc3 = 0.0f;
#pragma unroll
        for (int dx = 0; dx < 4; ++dx) {
            uint4 qa = bp[dx * 33];        // y-taps 0,1 (each: c01, c23)
            uint4 qb = bp[dx * 33 + 1];    // y-taps 2,3
            float2 a01 = h2f(qa.x), a23 = h2f(qa.y);
            float2 b01 = h2f(qa.z), b23 = h2f(qa.w);
            float2 c01 = h2f(qb.x), c23 = h2f(qb.y);
            float2 d01 = h2f(qb.z), d23 = h2f(qb.w);

            float r0 = a01.x * wy0 + b01.x * wy1 + c01.x * wy2 + d01.x * wy3;
            float r1 = a01.y * wy0 + b01.y * wy1 + c01.y * wy2 + d01.y * wy3;
            float r2 = a23.x * wy0 + b23.x * wy1 + c23.x * wy2 + d23.x * wy3;
            float r3 = a23.y * wy0 + b23.y * wy1 + c23.y * wy2 + d23.y * wy3;

            float wx = (dx == 0) ? wx0 : (dx == 1) ? wx1 : (dx == 2) ? wx2 : wx3;
            acc0 += wx * r0;
            acc1 += wx * r1;
            acc2 += wx * r2;
            acc3 += wx * r3;
        }
        out[i] = make_float4(acc0, acc1, acc2, acc3);
    }
}

extern "C" void kernel_launch(void* const* d_in, const int* in_sizes, int n_in,
                              void* d_out, int out_size)
{
    const float2* u    = (const float2*)d_in[0];
    const float*  data = (const float*)d_in[1];
    int n = in_sizes[0] / 2;

    cudaFuncSetAttribute(bspline_fused,
                         cudaFuncAttributeMaxDynamicSharedMemorySize, SMEM_BYTES);

    bspline_fused<<<296, 1024, SMEM_BYTES>>>(data, u, (float4*)d_out, n);
}